// round 10
// baseline (speedup 1.0000x reference)
#include <cuda_runtime.h>
#include <cuda_fp16.h>

// ---------------- problem constants ----------------
#define NN  100000      // nodes
#define NE  3200000     // edges (without self loops)
#define SB  512
#define NB_E 6250       // ceil(NE / SB)
#define CAP 128         // bucket capacity per dst (P(deg>128) ~ 1e-40)

// ---------------- scratch (device globals; no allocation) ----------------
__device__ __align__(16) __half g_h[NN * 64];     // h of current layer (fp16, gathered by edges)
__device__ __align__(16) float  g_h2f[NN * 64];   // layer-2 GEMM input (relu(norm+b1)), fp32
__device__ __align__(16) float  g_als[NN * 2];    // layer-1 src logits (2 heads)
__device__ __align__(16) float  g_ald[NN * 2];    // layer-1 dst logits
__device__ __align__(16) float  g_als2[NN];       // layer-2 src logits
__device__ __align__(16) float  g_ald2[NN];       // layer-2 dst logits
__device__ __align__(16) float  g_wa_s[64];       // W2 @ a_src2
__device__ __align__(16) float  g_wa_d[64];       // W2 @ a_dst2
// bucket CSR
__device__ int g_cnt[NN];
__device__ __align__(16) int g_csr[NN * CAP];     // 51.2 MB, 16B-aligned bucket rows

// ================= zero counters + prep (Wa = W2 @ a) =================
__global__ void zero_prep_kernel(const float* __restrict__ W2,
                                 const float* __restrict__ a_src, const float* __restrict__ a_dst)
{
    int nb = gridDim.x - 1;
    if ((int)blockIdx.x < nb) {
        int i = blockIdx.x * SB + threadIdx.x;
        if (i < NN) g_cnt[i] = 0;
    } else {
        int k = threadIdx.x;
        if (k < 64) {
            float s = 0.f, d = 0.f;
#pragma unroll 8
            for (int c = 0; c < 64; c++) {
                float w = W2[k * 64 + c];
                s += w * a_src[c];
                d += w * a_dst[c];
            }
            g_wa_s[k] = s;
            g_wa_d[k] = d;
        }
    }
}

// ================= fat: bucket fill + layer-1 node transform (independent) =================
__global__ __launch_bounds__(512) void fill_node1_kernel(
    const int* __restrict__ ei,
    const float* __restrict__ x, const int* __restrict__ type_ids,
    const float* __restrict__ type_emb, const float* __restrict__ W1,
    const float* __restrict__ a_src, const float* __restrict__ a_dst)
{
    if (blockIdx.x < NB_E) {
        // ---- bucket fill (no prefix sum needed) ----
        int i = blockIdx.x * SB + threadIdx.x;
        if (i < NE) {
            int dst = __ldg(ei + NE + i);
            int src = __ldg(ei + i);
            int pos = atomicAdd(&g_cnt[dst], 1);
            if (pos < CAP) g_csr[(dst << 7) + pos] = src;
        }
        return;
    }
    // ---- node1: 8 nodes per block, 512 threads (tx=col 0..63, ty=node 0..7) ----
    __shared__ float sW[21 * 64];
    __shared__ float sEmb[128];
    __shared__ float sX[8][5];
    __shared__ int   sT[8];
    __shared__ float sAs[64], sAd[64];

    int tid = threadIdx.x;
    int ty = tid >> 6, tx = tid & 63;

    for (int i = tid; i < 21 * 64; i += 512) sW[i] = W1[i];
    if (tid < 128) sEmb[tid] = type_emb[tid];
    if (tid >= 128 && tid < 192) { sAs[tid - 128] = a_src[tid - 128]; sAd[tid - 128] = a_dst[tid - 128]; }

    int node = (blockIdx.x - NB_E) * 8 + ty;   // NN % 8 == 0
    if (tx < 5) sX[ty][tx] = x[node * 5 + tx];
    if (tx == 5) sT[ty] = type_ids[node];
    __syncthreads();

    int col = tx;
    float acc = 0.f;
#pragma unroll
    for (int k = 0; k < 5; k++) acc += sX[ty][k] * sW[k * 64 + col];
    const float* emb = &sEmb[sT[ty] * 16];
#pragma unroll
    for (int k = 0; k < 16; k++) acc += emb[k] * sW[(5 + k) * 64 + col];

    // store h as fp16 (pack pairs via shfl; (2c,2c+1) always within one warp)
    float nxt = __shfl_down_sync(0xffffffffu, acc, 1);
    if ((col & 1) == 0) {
        __half2 p = __floats2half2_rn(acc, nxt);
        *(__half2*)(g_h + node * 64 + col) = p;
    }

    // per-head (32-col) reduction: cols 0-31 = head0 warp, 32-63 = head1 warp
    float s = acc * sAs[col], d = acc * sAd[col];
#pragma unroll
    for (int off = 16; off; off >>= 1) {
        s += __shfl_down_sync(0xffffffffu, s, off);
        d += __shfl_down_sync(0xffffffffu, d, off);
    }
    if ((col & 31) == 0) {
        int h = col >> 5;
        g_als[node * 2 + h] = s;
        g_ald[node * 2 + h] = d;
    }
}

// ================= bucket-CSR edge pass: one dst per WARP, 16 edges/iteration =================
// Lanes: cg = lane&15 covers channels cg*4..cg*4+3; half = lane>>4 takes a
// CONTIGUOUS 8-edge run (csr indices via two int4 loads). Cross-half combine
// via shfl_xor(16). Atomic-free.
// H==2 epilogue: relu(norm+b1) -> g_h2f, plus layer-2 logits via Wa reduction.
// H==1 epilogue: full LayerNorm in registers -> out.
template <int H>
__global__ __launch_bounds__(256, 4) void edge_csr_kernel(
    const float* __restrict__ b1,
    const float* __restrict__ b2, const float* __restrict__ gamma,
    const float* __restrict__ beta, float* __restrict__ out)
{
    int dst = blockIdx.x * 8 + (threadIdx.x >> 5);
    if (dst >= NN) return;
    int lane = threadIdx.x & 31;
    int cg   = lane & 15;
    int half = lane >> 4;
    int head = (H == 2) ? (cg >> 3) : 0;
    int base = dst << 7;
    int deg  = __ldg(&g_cnt[dst]);
    deg = deg < CAP ? deg : CAP;
    float adh = (H == 2) ? g_ald[dst * 2 + head] : g_ald2[dst];

    float a0 = 0.f, a1 = 0.f, a2 = 0.f, a3 = 0.f, esum = 0.f;

    // self loop (half 0 only)
    if (half == 0) {
        float l = ((H == 2) ? g_als[dst * 2 + head] : g_als2[dst]) + adh;
        l = l > 0.f ? l : 0.2f * l;
        float e = __expf(l);
        uint2 r = *(const uint2*)(g_h + dst * 64 + cg * 4);
        float2 f0 = __half22float2(*(__half2*)&r.x);
        float2 f1 = __half22float2(*(__half2*)&r.y);
        a0 += e * f0.x; a1 += e * f0.y; a2 += e * f1.x; a3 += e * f1.y;
        esum += e;
    }

    int j = base, end = base + deg;

    // main loop: 16 edges/iter; each half takes a contiguous 8-edge run.
    // csr bucket rows are 16B-aligned and j-base is a multiple of 16 here.
    for (; j + 16 <= end; j += 16) {
        int4 c0 = *(const int4*)(g_csr + j + half * 8);
        int4 c1 = *(const int4*)(g_csr + j + half * 8 + 4);
        int s[8] = {c0.x, c0.y, c0.z, c0.w, c1.x, c1.y, c1.z, c1.w};
        float l[8]; uint2 r[8];
#pragma unroll
        for (int u = 0; u < 8; u++)
            l[u] = ((H == 2) ? __ldg(g_als + s[u] * 2 + head) : __ldg(g_als2 + s[u])) + adh;
#pragma unroll
        for (int u = 0; u < 8; u++) r[u] = *(const uint2*)(g_h + s[u] * 64 + cg * 4);
#pragma unroll
        for (int u = 0; u < 8; u++) {
            float lu = l[u] > 0.f ? l[u] : 0.2f * l[u];
            float e = __expf(lu);
            float2 f0 = __half22float2(*(__half2*)&r[u].x);
            float2 f1 = __half22float2(*(__half2*)&r[u].y);
            a0 += e * f0.x; a1 += e * f0.y; a2 += e * f1.x; a3 += e * f1.y;
            esum += e;
        }
    }
    // 8-edge loop: each half takes a contiguous 4-edge run (one int4)
    for (; j + 8 <= end; j += 8) {
        int4 c0 = *(const int4*)(g_csr + j + half * 4);
        int s[4] = {c0.x, c0.y, c0.z, c0.w};
        float l[4]; uint2 r[4];
#pragma unroll
        for (int u = 0; u < 4; u++)
            l[u] = ((H == 2) ? __ldg(g_als + s[u] * 2 + head) : __ldg(g_als2 + s[u])) + adh;
#pragma unroll
        for (int u = 0; u < 4; u++) r[u] = *(const uint2*)(g_h + s[u] * 64 + cg * 4);
#pragma unroll
        for (int u = 0; u < 4; u++) {
            float lu = l[u] > 0.f ? l[u] : 0.2f * l[u];
            float e = __expf(lu);
            float2 f0 = __half22float2(*(__half2*)&r[u].x);
            float2 f1 = __half22float2(*(__half2*)&r[u].y);
            a0 += e * f0.x; a1 += e * f0.y; a2 += e * f1.x; a3 += e * f1.y;
            esum += e;
        }
    }
    // tail (0-7 edges); uniform trip count across warp, predicated access
    for (; j < end; j += 2) {
        int e = j + half;
        if (e < end) {
            int s = __ldg(g_csr + e);
            float l = ((H == 2) ? __ldg(g_als + s * 2 + head) : __ldg(g_als2 + s)) + adh;
            l = l > 0.f ? l : 0.2f * l;
            float ef = __expf(l);
            uint2 r = *(const uint2*)(g_h + s * 64 + cg * 4);
            float2 f0 = __half22float2(*(__half2*)&r.x);
            float2 f1 = __half22float2(*(__half2*)&r.y);
            a0 += ef * f0.x; a1 += ef * f0.y; a2 += ef * f1.x; a3 += ef * f1.y;
            esum += ef;
        }
    }

    // cross-half combine
    a0   += __shfl_xor_sync(0xffffffffu, a0, 16);
    a1   += __shfl_xor_sync(0xffffffffu, a1, 16);
    a2   += __shfl_xor_sync(0xffffffffu, a2, 16);
    a3   += __shfl_xor_sync(0xffffffffu, a3, 16);
    esum += __shfl_xor_sync(0xffffffffu, esum, 16);

    if (half == 0) {   // lanes 0-15 hold the full 64-channel result
        float inv = 1.f / (esum + 1e-16f);
        if (H == 2) {
            float4 b = *(const float4*)(b1 + cg * 4);
            float v0 = fmaxf(a0 * inv + b.x, 0.f);
            float v1 = fmaxf(a1 * inv + b.y, 0.f);
            float v2 = fmaxf(a2 * inv + b.z, 0.f);
            float v3 = fmaxf(a3 * inv + b.w, 0.f);
            *(float4*)(g_h2f + dst * 64 + cg * 4) = make_float4(v0, v1, v2, v3);
            // layer-2 logits: als2 = h2f . (W2 @ a_src2), ald2 likewise
            float4 ws = *(const float4*)(g_wa_s + cg * 4);
            float4 wd = *(const float4*)(g_wa_d + cg * 4);
            float ps = v0 * ws.x + v1 * ws.y + v2 * ws.z + v3 * ws.w;
            float pd = v0 * wd.x + v1 * wd.y + v2 * wd.z + v3 * wd.w;
#pragma unroll
            for (int off = 8; off; off >>= 1) {
                ps += __shfl_xor_sync(0x0000ffffu, ps, off);
                pd += __shfl_xor_sync(0x0000ffffu, pd, off);
            }
            if (cg == 0) { g_als2[dst] = ps; g_ald2[dst] = pd; }
        } else {
            // fused bias + LayerNorm, straight to output
            float4 b = *(const float4*)(b2 + cg * 4);
            float v0 = a0 * inv + b.x;
            float v1 = a1 * inv + b.y;
            float v2 = a2 * inv + b.z;
            float v3 = a3 * inv + b.w;
            float s = (v0 + v1) + (v2 + v3);
            float q = (v0 * v0 + v1 * v1) + (v2 * v2 + v3 * v3);
#pragma unroll
            for (int off = 8; off; off >>= 1) {
                s += __shfl_xor_sync(0x0000ffffu, s, off);
                q += __shfl_xor_sync(0x0000ffffu, q, off);
            }
            float mean = s * (1.f / 64.f);
            float var = q * (1.f / 64.f) - mean * mean;
            float istd = rsqrtf(var + 1e-5f);
            float4 g = *(const float4*)(gamma + cg * 4);
            float4 be = *(const float4*)(beta + cg * 4);
            float4 o;
            o.x = (v0 - mean) * istd * g.x + be.x;
            o.y = (v1 - mean) * istd * g.y + be.y;
            o.z = (v2 - mean) * istd * g.z + be.z;
            o.w = (v3 - mean) * istd * g.w + be.w;
            *(float4*)(out + dst * 64 + cg * 4) = o;
        }
    }
}

// ================= layer 2 node transform: h2 = g_h2f @ W2 (pure GEMM) =================
// Register-tiled: 256 threads, 128 nodes/block; thread = 4 nodes x 8 cols.
// 12 LDS.128 per 128 FMA (was 8 per 64) -> smem BW per FMA cut 25%.
__global__ __launch_bounds__(256) void node2_kernel(const float* __restrict__ W2)
{
    __shared__ float sW[64 * 64];          // 16 KB
    __shared__ float sIn[128 * 68];        // 128 nodes x 64 k, stride 68 (pad) = 34 KB

    int tid = threadIdx.x;
    int nbase = blockIdx.x * 128;

    for (int i = tid; i < 4096; i += 256) sW[i] = W2[i];

    // stage inputs (already relu(norm + b1), fp32)
    for (int i = tid; i < 2048; i += 256) {   // 128 nodes x 16 float4
        int n = i >> 4, c4 = i & 15;
        int gn = nbase + n;
        float4 v = make_float4(0.f, 0.f, 0.f, 0.f);
        if (gn < NN) v = *(const float4*)(g_h2f + gn * 64 + c4 * 4);
        *(float4*)&sIn[n * 68 + c4 * 4] = v;
    }
    __syncthreads();

    int cg = tid & 7;     // 8 output cols: cg*8 ..
    int ng = tid >> 3;    // 4 nodes: ng*4 ..

    float acc[4][8];
#pragma unroll
    for (int j = 0; j < 4; j++)
#pragma unroll
        for (int c = 0; c < 8; c++) acc[j][c] = 0.f;

#pragma unroll 4
    for (int k4 = 0; k4 < 16; k4++) {
        float in[4][4];
#pragma unroll
        for (int j = 0; j < 4; j++) {
            float4 v = *(const float4*)&sIn[(ng * 4 + j) * 68 + k4 * 4];
            in[j][0] = v.x; in[j][1] = v.y; in[j][2] = v.z; in[j][3] = v.w;
        }
#pragma unroll
        for (int kk = 0; kk < 4; kk++) {
            float4 w0 = *(const float4*)&sW[(k4 * 4 + kk) * 64 + cg * 8];
            float4 w1 = *(const float4*)&sW[(k4 * 4 + kk) * 64 + cg * 8 + 4];
#pragma unroll
            for (int j = 0; j < 4; j++) {
                float iv = in[j][kk];
                acc[j][0] += iv * w0.x;
                acc[j][1] += iv * w0.y;
                acc[j][2] += iv * w0.z;
                acc[j][3] += iv * w0.w;
                acc[j][4] += iv * w1.x;
                acc[j][5] += iv * w1.y;
                acc[j][6] += iv * w1.z;
                acc[j][7] += iv * w1.w;
            }
        }
    }

    // write h (fp16): 8 cols = 16B per node per thread
#pragma unroll
    for (int j = 0; j < 4; j++) {
        int n = nbase + ng * 4 + j;
        if (n >= NN) continue;
        __half2 p0 = __floats2half2_rn(acc[j][0], acc[j][1]);
        __half2 p1 = __floats2half2_rn(acc[j][2], acc[j][3]);
        __half2 p2 = __floats2half2_rn(acc[j][4], acc[j][5]);
        __half2 p3 = __floats2half2_rn(acc[j][6], acc[j][7]);
        uint4 raw;
        raw.x = *(unsigned*)&p0;
        raw.y = *(unsigned*)&p1;
        raw.z = *(unsigned*)&p2;
        raw.w = *(unsigned*)&p3;
        *(uint4*)(g_h + n * 64 + cg * 8) = raw;
    }
}

// ================= launch =================
extern "C" void kernel_launch(void* const* d_in, const int* in_sizes, int n_in,
                              void* d_out, int out_size)
{
    const float* x = nullptr; const int* ei = nullptr; const int* type_ids = nullptr;
    const float* type_emb = nullptr; const float* W1 = nullptr; const float* W2 = nullptr;
    const float* v64[8] = {nullptr};
    int c64 = 0;
    for (int i = 0; i < n_in; i++) {
        switch (in_sizes[i]) {
            case 500000:  x = (const float*)d_in[i]; break;
            case 6400000: ei = (const int*)d_in[i]; break;
            case 100000:  type_ids = (const int*)d_in[i]; break;
            case 128:     type_emb = (const float*)d_in[i]; break;
            case 1344:    W1 = (const float*)d_in[i]; break;
            case 4096:    W2 = (const float*)d_in[i]; break;
            case 64:      if (c64 < 8) v64[c64++] = (const float*)d_in[i]; break;
            default: break;
        }
    }
    const float* a_src1 = v64[0]; const float* a_dst1 = v64[1]; const float* b1 = v64[2];
    const float* a_src2 = v64[3]; const float* a_dst2 = v64[4]; const float* b2 = v64[5];
    const float* gamma = v64[6];  const float* beta = v64[7];
    float* out = (float*)d_out;

    const int NB_N   = (NN + SB - 1) / SB;    // 196
    const int NB_EDG = (NN + 7) / 8;          // 12500 (one dst per warp, 8 warps/block)

    // zero counters + Wa prep; then fill bucket CSR co-scheduled with node1
    zero_prep_kernel<<<NB_N + 1, SB>>>(W2, a_src2, a_dst2);
    fill_node1_kernel<<<NB_E + NN / 8, 512>>>(ei, x, type_ids, type_emb, W1, a_src1, a_dst1);

    // Layer 1 (2 heads x 32 ch): edge pass writes g_h2f + layer-2 logits
    edge_csr_kernel<2><<<NB_EDG, 256>>>(b1, nullptr, nullptr, nullptr, nullptr);

    // Layer 2 (1 head x 64 ch): pure GEMM, then edge pass with fused LayerNorm -> out
    node2_kernel<<<(NN + 127) / 128, 256>>>(W2);
    edge_csr_kernel<1><<<NB_EDG, 256>>>(nullptr, b2, gamma, beta, out);
}

// round 11
// speedup vs baseline: 1.0993x; 1.0993x over previous
#include <cuda_runtime.h>
#include <cuda_fp16.h>

// ---------------- problem constants ----------------
#define NN  100000      // nodes
#define NE  3200000     // edges (without self loops)
#define SB  512
#define NB_E 6250       // ceil(NE / SB)
#define CAP 128         // bucket capacity per dst (P(deg+1>128) ~ 1e-39)

// ---------------- scratch (device globals; no allocation) ----------------
__device__ __align__(16) __half g_h[NN * 64];     // h of current layer (fp16, gathered by edges)
__device__ __align__(16) float  g_h2f[NN * 64];   // layer-2 GEMM input (relu(norm+b1)), fp32
__device__ __align__(16) float  g_als[NN * 2];    // layer-1 src logits (2 heads)
__device__ __align__(16) float  g_ald[NN * 2];    // layer-1 dst logits
__device__ __align__(16) float  g_als2[NN];       // layer-2 src logits
__device__ __align__(16) float  g_ald2[NN];       // layer-2 dst logits
__device__ __align__(16) float  g_wa_s[64];       // W2 @ a_src2
__device__ __align__(16) float  g_wa_d[64];       // W2 @ a_dst2
// bucket CSR (slot 0 of each row = self loop, seeded by zero_prep)
__device__ int g_cnt[NN];
__device__ __align__(16) int g_csr[NN * CAP];     // 51.2 MB

// ================= seed counters (self loop) + prep (Wa = W2 @ a) =================
__global__ void zero_prep_kernel(const float* __restrict__ W2,
                                 const float* __restrict__ a_src, const float* __restrict__ a_dst)
{
    int nb = gridDim.x - 1;
    if ((int)blockIdx.x < nb) {
        int i = blockIdx.x * SB + threadIdx.x;
        if (i < NN) {
            g_cnt[i] = 1;              // slot 0 = self loop
            g_csr[i << 7] = i;
        }
    } else {
        int k = threadIdx.x;
        if (k < 64) {
            float s = 0.f, d = 0.f;
#pragma unroll 8
            for (int c = 0; c < 64; c++) {
                float w = W2[k * 64 + c];
                s += w * a_src[c];
                d += w * a_dst[c];
            }
            g_wa_s[k] = s;
            g_wa_d[k] = d;
        }
    }
}

// ================= fat: bucket fill + layer-1 node transform (independent) =================
__global__ __launch_bounds__(512) void fill_node1_kernel(
    const int* __restrict__ ei,
    const float* __restrict__ x, const int* __restrict__ type_ids,
    const float* __restrict__ type_emb, const float* __restrict__ W1,
    const float* __restrict__ a_src, const float* __restrict__ a_dst)
{
    if (blockIdx.x < NB_E) {
        // ---- bucket fill (no prefix sum needed) ----
        int i = blockIdx.x * SB + threadIdx.x;
        if (i < NE) {
            int dst = __ldg(ei + NE + i);
            int src = __ldg(ei + i);
            int pos = atomicAdd(&g_cnt[dst], 1);
            if (pos < CAP) g_csr[(dst << 7) + pos] = src;
        }
        return;
    }
    // ---- node1: 8 nodes per block, 512 threads (tx=col 0..63, ty=node 0..7) ----
    __shared__ float sW[21 * 64];
    __shared__ float sEmb[128];
    __shared__ float sX[8][5];
    __shared__ int   sT[8];
    __shared__ float sAs[64], sAd[64];

    int tid = threadIdx.x;
    int ty = tid >> 6, tx = tid & 63;

    for (int i = tid; i < 21 * 64; i += 512) sW[i] = W1[i];
    if (tid < 128) sEmb[tid] = type_emb[tid];
    if (tid >= 128 && tid < 192) { sAs[tid - 128] = a_src[tid - 128]; sAd[tid - 128] = a_dst[tid - 128]; }

    int node = (blockIdx.x - NB_E) * 8 + ty;   // NN % 8 == 0
    if (tx < 5) sX[ty][tx] = x[node * 5 + tx];
    if (tx == 5) sT[ty] = type_ids[node];
    __syncthreads();

    int col = tx;
    float acc = 0.f;
#pragma unroll
    for (int k = 0; k < 5; k++) acc += sX[ty][k] * sW[k * 64 + col];
    const float* emb = &sEmb[sT[ty] * 16];
#pragma unroll
    for (int k = 0; k < 16; k++) acc += emb[k] * sW[(5 + k) * 64 + col];

    // store h as fp16 (pack pairs via shfl; (2c,2c+1) always within one warp)
    float nxt = __shfl_down_sync(0xffffffffu, acc, 1);
    if ((col & 1) == 0) {
        __half2 p = __floats2half2_rn(acc, nxt);
        *(__half2*)(g_h + node * 64 + col) = p;
    }

    // per-head (32-col) reduction: cols 0-31 = head0 warp, 32-63 = head1 warp
    float s = acc * sAs[col], d = acc * sAd[col];
#pragma unroll
    for (int off = 16; off; off >>= 1) {
        s += __shfl_down_sync(0xffffffffu, s, off);
        d += __shfl_down_sync(0xffffffffu, d, off);
    }
    if ((col & 31) == 0) {
        int h = col >> 5;
        g_als[node * 2 + h] = s;
        g_ald[node * 2 + h] = d;
    }
}

// ================= bucket-CSR edge pass: one dst per WARP, two-phase =================
// Phase A: one (edge, head) per lane -> coalesced csr load, one als load, ONE
//          MUFU exp for 16 edges x H heads; esum lane-parallel.
// Phase B: shfl-broadcast (src, e); halves gather 8 h-rows each, FMA.
// H==2 epilogue: relu(norm+b1) -> g_h2f, plus layer-2 logits via Wa reduction.
// H==1 epilogue: full LayerNorm in registers -> out.
template <int H>
__global__ __launch_bounds__(256) void edge_csr_kernel(
    const float* __restrict__ b1,
    const float* __restrict__ b2, const float* __restrict__ gamma,
    const float* __restrict__ beta, float* __restrict__ out)
{
    int dst = blockIdx.x * 8 + (threadIdx.x >> 5);   // uniform per warp
    if (dst >= NN) return;
    int lane = threadIdx.x & 31;
    int cg   = lane & 15;
    int half = lane >> 4;
    int myhead = (H == 2) ? (cg >> 3) : 0;

    int base = dst << 7;
    int deg  = __ldg(&g_cnt[dst]);
    deg = deg < CAP ? deg : CAP;     // includes self loop (slot 0)

    // phase-A lane role
    int eidx, hh;
    float adh_a;
    if (H == 2) { eidx = lane >> 1; hh = lane & 1; adh_a = __ldg(g_ald + dst * 2 + hh); }
    else        { eidx = lane;      hh = 0;        adh_a = __ldg(g_ald2 + dst); }

    float a0 = 0.f, a1 = 0.f, a2 = 0.f, a3 = 0.f, esum_p = 0.f;

    for (int j = base; j < base + deg; j += 16) {
        int rem = base + deg - j;
        // ---- phase A ----
        bool valid = (eidx < rem) && (H == 2 || lane < 16);
        int s = valid ? __ldg(g_csr + j + eidx) : dst;
        float l = ((H == 2) ? __ldg(g_als + s * 2 + hh) : __ldg(g_als2 + s)) + adh_a;
        l = l > 0.f ? l : 0.2f * l;
        float e = valid ? __expf(l) : 0.f;
        esum_p += e;
        // ---- phase B: 16 edges, 8 per half ----
        int   srcs[8];
        float es[8];
#pragma unroll
        for (int u = 0; u < 8; u++) {
            int edge = half * 8 + u;
            int sl = (H == 2) ? (edge * 2 + myhead) : edge;
            srcs[u] = __shfl_sync(0xffffffffu, s, sl);
            es[u]   = __shfl_sync(0xffffffffu, e, sl);
        }
        uint2 r[8];
#pragma unroll
        for (int u = 0; u < 8; u++) r[u] = *(const uint2*)(g_h + srcs[u] * 64 + cg * 4);
#pragma unroll
        for (int u = 0; u < 8; u++) {
            float2 f0 = __half22float2(*(__half2*)&r[u].x);
            float2 f1 = __half22float2(*(__half2*)&r[u].y);
            a0 += es[u] * f0.x; a1 += es[u] * f0.y;
            a2 += es[u] * f1.x; a3 += es[u] * f1.y;
        }
    }

    // esum reduction
    float esum;
    if (H == 2) {
        // lanes hold per-(edge,head); head = lane&1. Sum within parity class.
        float t = esum_p;
#pragma unroll
        for (int off = 2; off <= 16; off <<= 1) t += __shfl_xor_sync(0xffffffffu, t, off);
        esum = __shfl_sync(0xffffffffu, t, myhead);   // lane 0 -> head0, lane 1 -> head1
    } else {
        float t = esum_p;
#pragma unroll
        for (int off = 1; off <= 16; off <<= 1) t += __shfl_xor_sync(0xffffffffu, t, off);
        esum = t;
    }

    // cross-half combine of channel accumulators (halves processed disjoint edges)
    a0 += __shfl_xor_sync(0xffffffffu, a0, 16);
    a1 += __shfl_xor_sync(0xffffffffu, a1, 16);
    a2 += __shfl_xor_sync(0xffffffffu, a2, 16);
    a3 += __shfl_xor_sync(0xffffffffu, a3, 16);

    if (half == 0) {   // lanes 0-15 hold the full 64-channel result
        float inv = 1.f / (esum + 1e-16f);
        if (H == 2) {
            float4 b = *(const float4*)(b1 + cg * 4);
            float v0 = fmaxf(a0 * inv + b.x, 0.f);
            float v1 = fmaxf(a1 * inv + b.y, 0.f);
            float v2 = fmaxf(a2 * inv + b.z, 0.f);
            float v3 = fmaxf(a3 * inv + b.w, 0.f);
            *(float4*)(g_h2f + dst * 64 + cg * 4) = make_float4(v0, v1, v2, v3);
            // layer-2 logits: als2 = h2f . (W2 @ a_src2), ald2 likewise
            float4 ws = *(const float4*)(g_wa_s + cg * 4);
            float4 wd = *(const float4*)(g_wa_d + cg * 4);
            float ps = v0 * ws.x + v1 * ws.y + v2 * ws.z + v3 * ws.w;
            float pd = v0 * wd.x + v1 * wd.y + v2 * wd.z + v3 * wd.w;
#pragma unroll
            for (int off = 8; off; off >>= 1) {
                ps += __shfl_xor_sync(0x0000ffffu, ps, off);
                pd += __shfl_xor_sync(0x0000ffffu, pd, off);
            }
            if (cg == 0) { g_als2[dst] = ps; g_ald2[dst] = pd; }
        } else {
            // fused bias + LayerNorm, straight to output
            float4 b = *(const float4*)(b2 + cg * 4);
            float v0 = a0 * inv + b.x;
            float v1 = a1 * inv + b.y;
            float v2 = a2 * inv + b.z;
            float v3 = a3 * inv + b.w;
            float s = (v0 + v1) + (v2 + v3);
            float q = (v0 * v0 + v1 * v1) + (v2 * v2 + v3 * v3);
#pragma unroll
            for (int off = 8; off; off >>= 1) {
                s += __shfl_xor_sync(0x0000ffffu, s, off);
                q += __shfl_xor_sync(0x0000ffffu, q, off);
            }
            float mean = s * (1.f / 64.f);
            float var = q * (1.f / 64.f) - mean * mean;
            float istd = rsqrtf(var + 1e-5f);
            float4 g = *(const float4*)(gamma + cg * 4);
            float4 be = *(const float4*)(beta + cg * 4);
            float4 o;
            o.x = (v0 - mean) * istd * g.x + be.x;
            o.y = (v1 - mean) * istd * g.y + be.y;
            o.z = (v2 - mean) * istd * g.z + be.z;
            o.w = (v3 - mean) * istd * g.w + be.w;
            *(float4*)(out + dst * 64 + cg * 4) = o;
        }
    }
}

// ================= layer 2 node transform: h2 = g_h2f @ W2 (pure GEMM) =================
// Register-tiled (R9 version): 256 threads, 64 nodes/block; thread = 4 nodes x 4 cols.
__global__ __launch_bounds__(256) void node2_kernel(const float* __restrict__ W2)
{
    __shared__ float sW[64 * 64];          // 16 KB
    __shared__ float sIn[64 * 68];         // 64 nodes x 64 k, stride 68 (pad)

    int tid = threadIdx.x;
    int nbase = blockIdx.x * 64;

    for (int i = tid; i < 4096; i += 256) sW[i] = W2[i];

    // stage inputs (already relu(norm + b1), fp32)
    for (int i = tid; i < 1024; i += 256) {   // 64 nodes x 16 float4
        int n = i >> 4, c4 = i & 15;
        int gn = nbase + n;
        float4 v = make_float4(0.f, 0.f, 0.f, 0.f);
        if (gn < NN) v = *(const float4*)(g_h2f + gn * 64 + c4 * 4);
        *(float4*)&sIn[n * 68 + c4 * 4] = v;
    }
    __syncthreads();

    int cg = tid & 15;    // 4 output cols: cg*4 ..
    int ng = tid >> 4;    // 4 nodes: ng*4 ..

    float acc[4][4];
#pragma unroll
    for (int j = 0; j < 4; j++)
#pragma unroll
        for (int c = 0; c < 4; c++) acc[j][c] = 0.f;

#pragma unroll 4
    for (int k4 = 0; k4 < 16; k4++) {
        float in[4][4];
#pragma unroll
        for (int j = 0; j < 4; j++) {
            float4 v = *(const float4*)&sIn[(ng * 4 + j) * 68 + k4 * 4];
            in[j][0] = v.x; in[j][1] = v.y; in[j][2] = v.z; in[j][3] = v.w;
        }
#pragma unroll
        for (int kk = 0; kk < 4; kk++) {
            float4 w = *(const float4*)&sW[(k4 * 4 + kk) * 64 + cg * 4];
#pragma unroll
            for (int j = 0; j < 4; j++) {
                acc[j][0] += in[j][kk] * w.x;
                acc[j][1] += in[j][kk] * w.y;
                acc[j][2] += in[j][kk] * w.z;
                acc[j][3] += in[j][kk] * w.w;
            }
        }
    }

    // write h (fp16)
#pragma unroll
    for (int j = 0; j < 4; j++) {
        int n = nbase + ng * 4 + j;
        if (n >= NN) continue;
        __half2 p0 = __floats2half2_rn(acc[j][0], acc[j][1]);
        __half2 p1 = __floats2half2_rn(acc[j][2], acc[j][3]);
        uint2 raw;
        raw.x = *(unsigned*)&p0;
        raw.y = *(unsigned*)&p1;
        *(uint2*)(g_h + n * 64 + cg * 4) = raw;
    }
}

// ================= launch =================
extern "C" void kernel_launch(void* const* d_in, const int* in_sizes, int n_in,
                              void* d_out, int out_size)
{
    const float* x = nullptr; const int* ei = nullptr; const int* type_ids = nullptr;
    const float* type_emb = nullptr; const float* W1 = nullptr; const float* W2 = nullptr;
    const float* v64[8] = {nullptr};
    int c64 = 0;
    for (int i = 0; i < n_in; i++) {
        switch (in_sizes[i]) {
            case 500000:  x = (const float*)d_in[i]; break;
            case 6400000: ei = (const int*)d_in[i]; break;
            case 100000:  type_ids = (const int*)d_in[i]; break;
            case 128:     type_emb = (const float*)d_in[i]; break;
            case 1344:    W1 = (const float*)d_in[i]; break;
            case 4096:    W2 = (const float*)d_in[i]; break;
            case 64:      if (c64 < 8) v64[c64++] = (const float*)d_in[i]; break;
            default: break;
        }
    }
    const float* a_src1 = v64[0]; const float* a_dst1 = v64[1]; const float* b1 = v64[2];
    const float* a_src2 = v64[3]; const float* a_dst2 = v64[4]; const float* b2 = v64[5];
    const float* gamma = v64[6];  const float* beta = v64[7];
    float* out = (float*)d_out;

    const int NB_N   = (NN + SB - 1) / SB;    // 196
    const int NB_EDG = (NN + 7) / 8;          // 12500 (one dst per warp, 8 warps/block)

    // seed counters (self loops) + Wa prep; then fill bucket CSR co-scheduled with node1
    zero_prep_kernel<<<NB_N + 1, SB>>>(W2, a_src2, a_dst2);
    fill_node1_kernel<<<NB_E + NN / 8, 512>>>(ei, x, type_ids, type_emb, W1, a_src1, a_dst1);

    // Layer 1 (2 heads x 32 ch): edge pass writes g_h2f + layer-2 logits
    edge_csr_kernel<2><<<NB_EDG, 256>>>(b1, nullptr, nullptr, nullptr, nullptr);

    // Layer 2 (1 head x 64 ch): pure GEMM, then edge pass with fused LayerNorm -> out
    node2_kernel<<<(NN + 63) / 64, 256>>>(W2);
    edge_csr_kernel<1><<<NB_EDG, 256>>>(nullptr, b2, gamma, beta, out);
}